// round 16
// baseline (speedup 1.0000x reference)
#include <cuda_runtime.h>
#include <cuda_fp16.h>
#include <math.h>
#include <stdint.h>

// ---------------- problem constants ----------------
#define NN 50000
#define EMAX 800000
#define DIN 256
#define DHID 128
#define DOUT 64
#define NGRAPH 16
#define BN_EPS 1e-5f
#define SCAN_B 256

// ---------------- device scratch ----------------
__device__ __align__(16) float g_dinv[NN];
__device__ __align__(16) int   g_cnt[NN];
__device__ __align__(16) int   g_off[NN + 1];
__device__ __align__(16) int   g_bsum[SCAN_B];
__device__ int g_ctrA, g_ctrP;
__device__ __align__(16) int2  g_edges[EMAX];
__device__ __align__(16) __half g_hX[NN * DIN];    // fp16 copy of input x
__device__ __align__(16) __half g_hA[NN * DHID];
__device__ __align__(16) __half g_hB[NN * DHID];
__device__ __align__(16) __half g_hC[NN * DOUT];
__device__ __align__(16) float g_agg3[NN * DOUT];
__device__ __align__(16) __half g_w1h[DIN * DHID],  g_w1l[DIN * DHID];
__device__ __align__(16) __half g_w2h[DHID * DHID], g_w2l[DHID * DHID];
__device__ __align__(16) __half g_w3h[DHID * DOUT], g_w3l[DHID * DOUT];
__device__ __align__(16) float g_statA_s[DHID], g_statA_q[DHID];
__device__ __align__(16) float g_statB_s[DHID], g_statB_q[DHID];
__device__ __align__(16) float g_bnsum[DHID];    // BN scale
__device__ __align__(16) float g_bnsq[DHID];     // BN shift
__device__ __align__(16) float g_pool[NGRAPH * DOUT];
__device__ __align__(16) float g_pcnt[NGRAPH];

#define WTOTAL (DIN * DHID + DHID * DHID + DHID * DOUT)

// ---------------- fused init: x->fp16, W prep, zero state ----------------
// Each thread in the xconv range converts 8 floats (2 float4 -> 1 uint4).
__global__ void k_init0(const float* __restrict__ x,
                        const float* __restrict__ W1,
                        const float* __restrict__ W2,
                        const float* __restrict__ W3, int n) {
    int i = blockIdx.x * blockDim.x + threadIdx.x;
    int nxc = n * (DIN / 8);
    if (i < nxc) {
        float4 a = *reinterpret_cast<const float4*>(&x[(size_t)i * 8]);
        float4 b = *reinterpret_cast<const float4*>(&x[(size_t)i * 8 + 4]);
        uint4 o;
        __half2* op = reinterpret_cast<__half2*>(&o);
        op[0] = __floats2half2_rn(a.x, a.y);
        op[1] = __floats2half2_rn(a.z, a.w);
        op[2] = __floats2half2_rn(b.x, b.y);
        op[3] = __floats2half2_rn(b.z, b.w);
        *reinterpret_cast<uint4*>(&g_hX[(size_t)i * 8]) = o;
    }
    if (i < WTOTAL) {
        const float* W; __half* Hh; __half* Hl; int K, N, j;
        if (i < DIN * DHID) {
            W = W1; Hh = g_w1h; Hl = g_w1l; K = DIN; N = DHID; j = i;
        } else if (i < DIN * DHID + DHID * DHID) {
            W = W2; Hh = g_w2h; Hl = g_w2l; K = DHID; N = DHID; j = i - DIN * DHID;
        } else {
            W = W3; Hh = g_w3h; Hl = g_w3l; K = DHID; N = DOUT;
            j = i - DIN * DHID - DHID * DHID;
        }
        int k = j / N, nn = j % N;
        float v = W[j];
        __half h = __float2half_rn(v);
        Hh[nn * K + k] = h;
        Hl[nn * K + k] = __float2half_rn(v - __half2float(h));
    }
    if (i < n) g_cnt[i] = 0;
    if (i < DHID) {
        g_statA_s[i] = 0.0f; g_statA_q[i] = 0.0f;
        g_statB_s[i] = 0.0f; g_statB_q[i] = 0.0f;
    }
    if (i < NGRAPH * DOUT) g_pool[i] = 0.0f;
    if (i < NGRAPH) g_pcnt[i] = 0.0f;
    if (i == 0) { g_ctrA = 0; g_ctrP = 0; }
}

// ---------------- degree count ----------------
__global__ void k_cnt(const int* __restrict__ dst, int e, int n) {
    int i = blockIdx.x * blockDim.x + threadIdx.x;
    if (i < e) {
        int d = dst[i];
        if ((unsigned)d < (unsigned)n) atomicAdd(&g_cnt[d], 1);
    }
}

// ---------------- scan A+B fused (last-block), + dinv ----------------
__global__ void k_scanAB(int n, int nblocks) {
    __shared__ int sh[SCAN_B];
    __shared__ bool isLast;
    int t = threadIdx.x;
    int i = blockIdx.x * SCAN_B + t;
    int cv = (i < n) ? g_cnt[i] : 0;
    if (i < n) g_dinv[i] = rsqrtf((float)cv + 1.0f);
    sh[t] = cv;
    __syncthreads();
#pragma unroll
    for (int d = SCAN_B / 2; d > 0; d >>= 1) {
        if (t < d) sh[t] += sh[t + d];
        __syncthreads();
    }
    if (t == 0) {
        g_bsum[blockIdx.x] = sh[0];
        __threadfence();
        int old = atomicAdd(&g_ctrA, 1);
        isLast = (old == nblocks - 1);
    }
    __syncthreads();
    if (isLast) {
        __threadfence();
        int v = (t < nblocks) ? g_bsum[t] : 0;
        sh[t] = v;
        __syncthreads();
#pragma unroll
        for (int d = 1; d < SCAN_B; d <<= 1) {
            int x = (t >= d) ? sh[t - d] : 0;
            __syncthreads();
            sh[t] += x;
            __syncthreads();
        }
        if (t < nblocks) g_bsum[t] = sh[t] - v;
        if (t == SCAN_B - 1) g_off[n] = sh[t];
    }
}

__global__ void k_scanC(int n) {
    __shared__ int sh[SCAN_B];
    int t = threadIdx.x;
    int i = blockIdx.x * SCAN_B + t;
    int v = (i < n) ? g_cnt[i] : 0;
    sh[t] = v;
    __syncthreads();
#pragma unroll
    for (int d = 1; d < SCAN_B; d <<= 1) {
        int x = (t >= d) ? sh[t - d] : 0;
        __syncthreads();
        sh[t] += x;
        __syncthreads();
    }
    if (i < n) {
        int off = g_bsum[blockIdx.x] + sh[t] - v;
        g_off[i] = off;
        g_cnt[i] = off;
    }
}

__global__ void k_fill(const int* __restrict__ src, const int* __restrict__ dst,
                       int e, int n) {
    int i = blockIdx.x * blockDim.x + threadIdx.x;
    if (i >= e) return;
    int s = src[i], d = dst[i];
    if ((unsigned)s >= (unsigned)n || (unsigned)d >= (unsigned)n) return;
    float w = g_dinv[s] * g_dinv[d];
    int pos = atomicAdd(&g_cnt[d], 1);
    g_edges[pos] = make_int2(s, __float_as_int(w));
}

// ---------------- mma / ldmatrix helpers ----------------
#define MMA_F16(d, a, b0, b1)                                               \
    asm volatile(                                                           \
        "mma.sync.aligned.m16n8k16.row.col.f32.f16.f16.f32 "                \
        "{%0,%1,%2,%3}, {%4,%5,%6,%7}, {%8,%9}, {%0,%1,%2,%3};"             \
        : "+f"((d)[0]), "+f"((d)[1]), "+f"((d)[2]), "+f"((d)[3])            \
        : "r"((a)[0]), "r"((a)[1]), "r"((a)[2]), "r"((a)[3]),               \
          "r"(b0), "r"(b1))

__device__ __forceinline__ void ldsm_x4(uint32_t addr, unsigned* r) {
    asm volatile("ldmatrix.sync.aligned.m8n8.x4.shared.b16 {%0,%1,%2,%3}, [%4];"
                 : "=r"(r[0]), "=r"(r[1]), "=r"(r[2]), "=r"(r[3]) : "r"(addr));
}

// ---------------- tensor-core GEMM: 2-pass fp16, fp16 input, ldmatrix ------
// OUT (fp16) = T(X) @ W.  T: identity or BN-affine(g_bnsum/g_bnsq)+ReLU.
template <int KDIM, int NOUT, bool BNRELU>
__global__ void __launch_bounds__(256, 2)
k_gemm_f16(const __half* __restrict__ X, const __half* __restrict__ Whg,
           const __half* __restrict__ Wlg, __half* __restrict__ OUT, int nrows) {
    constexpr int BM = 128, BK = 16, KS = 24;     // 48B row stride
    constexpr int hN = NOUT / 2;
    constexpr int NT = hN / 8;                    // 8 or 4
    constexpr int NP = NT / 2;                    // ldmatrix n-pairs (4 or 2)
    constexpr int MT = 2;
    constexpr int KT = KDIM / BK;
    constexpr int WL = (NOUT == 128) ? 8 : 4;

    __shared__ __half Xs[2][BM][KS];
    __shared__ __half Wh[2][NOUT][KS], Wl[2][NOUT][KS];

    const int tid = threadIdx.x;
    const int lane = tid & 31;
    const int wid = tid >> 5;
    const int wm = wid & 3, wn = wid >> 2;
    const int row0 = blockIdx.x * BM;

    const int xr = tid >> 1;
    const int xkp = (tid & 1) * 8;
    const int wr = (NOUT == 128) ? (tid >> 1) : (tid >> 2);
    const int wkp = (NOUT == 128) ? (tid & 1) * 8 : (tid & 3) * 4;

    const int grp = lane >> 3, lr = lane & 7;
    const uint32_t xsBase = (uint32_t)__cvta_generic_to_shared(&Xs[0][0][0]);
    const uint32_t whBase = (uint32_t)__cvta_generic_to_shared(&Wh[0][0][0]);
    const uint32_t wlBase = (uint32_t)__cvta_generic_to_shared(&Wl[0][0][0]);
    const uint32_t xsStage = BM * KS * 2;
    const uint32_t wStage  = NOUT * KS * 2;
    uint32_t aOff[MT];
#pragma unroll
    for (int mt = 0; mt < MT; mt++) {
        int r = wm * 32 + mt * 16 + (grp & 1) * 8 + lr;
        aOff[mt] = (uint32_t)(r * KS * 2 + (grp >> 1) * 16);
    }
    uint32_t bOff[NP];
#pragma unroll
    for (int p = 0; p < NP; p++) {
        int r = wn * hN + p * 16 + (grp >> 1) * 8 + lr;
        bOff[p] = (uint32_t)(r * KS * 2 + (grp & 1) * 16);
    }

    float acc[MT][NT][4] = {};
    uint4 xu;
    __half wvh[WL], wvl[WL];

    auto fetch = [&](int kb) {
        int row = row0 + xr;
        xu = make_uint4(0, 0, 0, 0);
        if (row < nrows)
            xu = *reinterpret_cast<const uint4*>(&X[(size_t)row * KDIM + kb + xkp]);
        const __half* ph = &Whg[(size_t)wr * KDIM + kb + wkp];
        const __half* pl = &Wlg[(size_t)wr * KDIM + kb + wkp];
        if (WL == 8) {
            *reinterpret_cast<uint4*>(wvh) = *reinterpret_cast<const uint4*>(ph);
            *reinterpret_cast<uint4*>(wvl) = *reinterpret_cast<const uint4*>(pl);
        } else {
            *reinterpret_cast<uint2*>(wvh) = *reinterpret_cast<const uint2*>(ph);
            *reinterpret_cast<uint2*>(wvl) = *reinterpret_cast<const uint2*>(pl);
        }
    };

    auto stage = [&](int kb, int s) {
        if (BNRELU) {
            const __half2* hp = reinterpret_cast<const __half2*>(&xu);
            __half hx[8];
#pragma unroll
            for (int j = 0; j < 4; j++) {
                float2 f = __half22float2(hp[j]);
                float v0 = fmaxf(fmaf(f.x, g_bnsum[kb + xkp + 2 * j],
                                      g_bnsq[kb + xkp + 2 * j]), 0.f);
                float v1 = fmaxf(fmaf(f.y, g_bnsum[kb + xkp + 2 * j + 1],
                                      g_bnsq[kb + xkp + 2 * j + 1]), 0.f);
                *reinterpret_cast<__half2*>(&hx[2 * j]) = __floats2half2_rn(v0, v1);
            }
            *reinterpret_cast<uint4*>(&Xs[s][xr][xkp]) = *reinterpret_cast<uint4*>(hx);
        } else {
            *reinterpret_cast<uint4*>(&Xs[s][xr][xkp]) = xu;
        }
        if (WL == 8) {
            *reinterpret_cast<uint4*>(&Wh[s][wr][wkp]) = *reinterpret_cast<uint4*>(wvh);
            *reinterpret_cast<uint4*>(&Wl[s][wr][wkp]) = *reinterpret_cast<uint4*>(wvl);
        } else {
            *reinterpret_cast<uint2*>(&Wh[s][wr][wkp]) = *reinterpret_cast<uint2*>(wvh);
            *reinterpret_cast<uint2*>(&Wl[s][wr][wkp]) = *reinterpret_cast<uint2*>(wvl);
        }
    };

    fetch(0);
    stage(0, 0);
    __syncthreads();

    for (int kt = 0; kt < KT; kt++) {
        const int s = kt & 1;
        const bool more = (kt + 1 < KT);
        if (more) fetch((kt + 1) * BK);

        unsigned ah[MT][4];
#pragma unroll
        for (int mt = 0; mt < MT; mt++)
            ldsm_x4(xsBase + s * xsStage + aOff[mt], ah[mt]);

#pragma unroll
        for (int p = 0; p < NP; p++) {
            unsigned bh[4], bl[4];
            ldsm_x4(whBase + s * wStage + bOff[p], bh);
            ldsm_x4(wlBase + s * wStage + bOff[p], bl);
#pragma unroll
            for (int mt = 0; mt < MT; mt++) {
                MMA_F16(acc[mt][2 * p],     ah[mt], bh[0], bh[1]);
                MMA_F16(acc[mt][2 * p + 1], ah[mt], bh[2], bh[3]);
            }
#pragma unroll
            for (int mt = 0; mt < MT; mt++) {
                MMA_F16(acc[mt][2 * p],     ah[mt], bl[0], bl[1]);
                MMA_F16(acc[mt][2 * p + 1], ah[mt], bl[2], bl[3]);
            }
        }

        if (more) stage((kt + 1) * BK, s ^ 1);
        __syncthreads();
    }

    const int rfo = lane >> 2;
#pragma unroll
    for (int mt = 0; mt < MT; mt++) {
        int r0 = row0 + wm * 32 + mt * 16 + rfo;
        int r1 = r0 + 8;
#pragma unroll
        for (int nt = 0; nt < NT; nt++) {
            int col = wn * hN + nt * 8 + (lane & 3) * 2;
            if (r0 < nrows)
                *reinterpret_cast<__half2*>(&OUT[(size_t)r0 * NOUT + col]) =
                    __floats2half2_rn(acc[mt][nt][0], acc[mt][nt][1]);
            if (r1 < nrows)
                *reinterpret_cast<__half2*>(&OUT[(size_t)r1 * NOUT + col]) =
                    __floats2half2_rn(acc[mt][nt][2], acc[mt][nt][3]);
        }
    }
}

// ---------------- fp16 gather helper ----------------
__device__ __forceinline__ void fma8h(uint4 u, float w, float* acc) {
    const __half2* hp = reinterpret_cast<const __half2*>(&u);
#pragma unroll
    for (int j = 0; j < 4; j++) {
        float2 f = __half22float2(hp[j]);
        acc[2 * j]     = fmaf(f.x, w, acc[2 * j]);
        acc[2 * j + 1] = fmaf(f.y, w, acc[2 * j + 1]);
    }
}

// ---------------- CSR aggregation (fp16 gather, fp32 accumulate) ------------
template <int NOUT, bool BNSTAT, bool OUTF32>
__global__ void __launch_bounds__(256, 4)
k_aggr(const __half* __restrict__ h, float* __restrict__ outf,
       __half* __restrict__ outh, float* __restrict__ stat_s,
       float* __restrict__ stat_q, int n) {
    constexpr int LPN = NOUT / 8;
    constexpr int NPW = 32 / LPN;
    constexpr int NPB = 8 * NPW;
    __shared__ float ss[BNSTAT ? DHID : 1], sq[BNSTAT ? DHID : 1];

    int tid = threadIdx.x;
    int warp = tid >> 5, lane = tid & 31;
    if (BNSTAT) {
        if (tid < NOUT) { ss[tid] = 0.0f; sq[tid] = 0.0f; }
        __syncthreads();
    }

    int node = blockIdx.x * NPB + warp * NPW + lane / LPN;
    int c = (lane % LPN) * 8;
    float acc[8] = {};
    bool active = (node < n);

    if (active) {
        float di = g_dinv[node];
        di *= di;
        {
            uint4 u = *reinterpret_cast<const uint4*>(&h[(size_t)node * NOUT + c]);
            const __half2* hp = reinterpret_cast<const __half2*>(&u);
#pragma unroll
            for (int j = 0; j < 4; j++) {
                float2 f = __half22float2(hp[j]);
                acc[2 * j] = f.x * di;
                acc[2 * j + 1] = f.y * di;
            }
        }

        int i = g_off[node], e1 = g_off[node + 1];
        for (; i + 4 <= e1; i += 4) {
            int2 e0 = g_edges[i + 0];
            int2 e1r = g_edges[i + 1];
            int2 e2 = g_edges[i + 2];
            int2 e3 = g_edges[i + 3];
            uint4 u0 = *reinterpret_cast<const uint4*>(&h[(size_t)e0.x * NOUT + c]);
            uint4 u1 = *reinterpret_cast<const uint4*>(&h[(size_t)e1r.x * NOUT + c]);
            uint4 u2 = *reinterpret_cast<const uint4*>(&h[(size_t)e2.x * NOUT + c]);
            uint4 u3 = *reinterpret_cast<const uint4*>(&h[(size_t)e3.x * NOUT + c]);
            fma8h(u0, __int_as_float(e0.y), acc);
            fma8h(u1, __int_as_float(e1r.y), acc);
            fma8h(u2, __int_as_float(e2.y), acc);
            fma8h(u3, __int_as_float(e3.y), acc);
        }
        if (i + 2 <= e1) {
            int2 e0 = g_edges[i + 0];
            int2 e1r = g_edges[i + 1];
            uint4 u0 = *reinterpret_cast<const uint4*>(&h[(size_t)e0.x * NOUT + c]);
            uint4 u1 = *reinterpret_cast<const uint4*>(&h[(size_t)e1r.x * NOUT + c]);
            fma8h(u0, __int_as_float(e0.y), acc);
            fma8h(u1, __int_as_float(e1r.y), acc);
            i += 2;
        }
        if (i < e1) {
            int2 e = g_edges[i];
            uint4 u = *reinterpret_cast<const uint4*>(&h[(size_t)e.x * NOUT + c]);
            fma8h(u, __int_as_float(e.y), acc);
        }

        if (OUTF32) {
            float4 a = make_float4(acc[0], acc[1], acc[2], acc[3]);
            float4 b = make_float4(acc[4], acc[5], acc[6], acc[7]);
            *reinterpret_cast<float4*>(&outf[(size_t)node * NOUT + c]) = a;
            *reinterpret_cast<float4*>(&outf[(size_t)node * NOUT + c + 4]) = b;
        } else {
            uint4 o;
            __half2* op = reinterpret_cast<__half2*>(&o);
            op[0] = __floats2half2_rn(acc[0], acc[1]);
            op[1] = __floats2half2_rn(acc[2], acc[3]);
            op[2] = __floats2half2_rn(acc[4], acc[5]);
            op[3] = __floats2half2_rn(acc[6], acc[7]);
            *reinterpret_cast<uint4*>(&outh[(size_t)node * NOUT + c]) = o;
        }
    }

    if (BNSTAT) {
        if (active) {
#pragma unroll
            for (int j = 0; j < 8; j++) {
                atomicAdd(&ss[c + j], acc[j]);
                atomicAdd(&sq[c + j], acc[j] * acc[j]);
            }
        }
        __syncthreads();
        if (tid < NOUT) {
            atomicAdd(&stat_s[tid], ss[tid]);
            atomicAdd(&stat_q[tid], sq[tid]);
        }
    }
}

// ---------------- BN finalize: raw stats -> (scale, shift) ----------------
__global__ void k_bnfinal(const float* __restrict__ gam, const float* __restrict__ bet,
                          const float* __restrict__ stat_s,
                          const float* __restrict__ stat_q, float n) {
    int c = threadIdx.x;  // 128
    float mu = stat_s[c] / n;
    float var = stat_q[c] / n - mu * mu;
    float sc = rsqrtf(var + BN_EPS) * gam[c];
    g_bnsum[c] = sc;
    g_bnsq[c] = bet[c] - mu * sc;
}

// ---------------- pool + final fused (last-block) ----------------
#define POOL_CHUNK 128
__global__ void k_pool_final(const float* __restrict__ h, const int* __restrict__ batch,
                             int n, int nbp, float* __restrict__ out,
                             const float* __restrict__ b3) {
    __shared__ bool isLast;
    int col = threadIdx.x;  // 64
    int r0 = blockIdx.x * POOL_CHUNK;
    int r1 = min(r0 + POOL_CHUNK, n);
    if (r0 < n) {
        int cur = batch[r0] & (NGRAPH - 1);
        float acc = 0.0f, cacc = 0.0f;
        for (int r = r0; r < r1; r++) {
            int g = batch[r] & (NGRAPH - 1);
            if (g != cur) {
                atomicAdd(&g_pool[cur * DOUT + col], acc);
                if (col == 0) atomicAdd(&g_pcnt[cur], cacc);
                acc = 0.0f; cacc = 0.0f; cur = g;
            }
            acc += h[(size_t)r * DOUT + col];
            cacc += 1.0f;
        }
        atomicAdd(&g_pool[cur * DOUT + col], acc);
        if (col == 0) atomicAdd(&g_pcnt[cur], cacc);
    }
    __threadfence();
    if (col == 0) {
        int old = atomicAdd(&g_ctrP, 1);
        isLast = (old == nbp - 1);
    }
    __syncthreads();
    if (isLast) {
        __threadfence();
        for (int t = col; t < NGRAPH * DOUT; t += blockDim.x) {
            int g = t / DOUT, c = t % DOUT;
            float cnt = g_pcnt[g];
            out[t] = (cnt > 0.0f) ? (g_pool[t] / cnt + b3[c]) : 0.0f;
        }
    }
}

// ============================================================================
extern "C" void kernel_launch(void* const* d_in, const int* in_sizes, int n_in,
                              void* d_out, int out_size) {
    const float* x     = (const float*)d_in[0];
    const int*   ei    = (const int*)d_in[1];   // int64 coerced to int32
    const int*   batch = (const int*)d_in[2];
    const float* W1    = (const float*)d_in[3];
    const float* W2    = (const float*)d_in[5];
    const float* W3    = (const float*)d_in[7];
    const float* b3    = (const float*)d_in[8];
    const float* g1    = (const float*)d_in[9];
    const float* be1   = (const float*)d_in[10];
    const float* g2    = (const float*)d_in[11];
    const float* be2   = (const float*)d_in[12];
    float* out = (float*)d_out;

    const int n = in_sizes[2];       // 50000
    const int E = in_sizes[1] / 2;   // 800000
    const int* src = ei;
    const int* dst = ei + E;

    __half* hX; __half* hA; __half* hB; __half* hC; float* agg3;
    cudaGetSymbolAddress((void**)&hX, g_hX);
    cudaGetSymbolAddress((void**)&hA, g_hA);
    cudaGetSymbolAddress((void**)&hB, g_hB);
    cudaGetSymbolAddress((void**)&hC, g_hC);
    cudaGetSymbolAddress((void**)&agg3, g_agg3);
    __half *w1h, *w1l, *w2h, *w2l, *w3h, *w3l;
    cudaGetSymbolAddress((void**)&w1h, g_w1h);
    cudaGetSymbolAddress((void**)&w1l, g_w1l);
    cudaGetSymbolAddress((void**)&w2h, g_w2h);
    cudaGetSymbolAddress((void**)&w2l, g_w2l);
    cudaGetSymbolAddress((void**)&w3h, g_w3h);
    cudaGetSymbolAddress((void**)&w3l, g_w3l);
    float *sAs, *sAq, *sBs, *sBq;
    cudaGetSymbolAddress((void**)&sAs, g_statA_s);
    cudaGetSymbolAddress((void**)&sAq, g_statA_q);
    cudaGetSymbolAddress((void**)&sBs, g_statB_s);
    cudaGetSymbolAddress((void**)&sBq, g_statB_q);

    const int TB = 256;
    int nxc     = n * (DIN / 8);                 // x-conversion threads
    int init_n  = nxc;                           // nxc dominates WTOTAL and n
    int nb_init = (init_n + TB - 1) / TB;
    int nb_e    = (E + TB - 1) / TB;
    int nb_scan = (n + SCAN_B - 1) / SCAN_B;
    int nb_gemm = (n + 127) / 128;
    int nb_ag128 = (n + 15) / 16;
    int nb_ag64  = (n + 31) / 32;
    int nb_pool  = (n + POOL_CHUNK - 1) / POOL_CHUNK;
    float fn = (float)n;

    // 14 launches; gemm1 at stream position 4 (ncu capture slot).
    k_init0<<<nb_init, TB>>>(x, W1, W2, W3, n);                                // 1
    k_cnt<<<nb_e, TB>>>(dst, E, n);                                            // 2
    k_scanAB<<<nb_scan, SCAN_B>>>(n, nb_scan);                                 // 3
    k_gemm_f16<256, 128, false><<<nb_gemm, 256>>>(hX, w1h, w1l, hA, n);        // 4
    k_scanC<<<nb_scan, SCAN_B>>>(n);                                           // 5
    k_fill<<<nb_e, TB>>>(src, dst, E, n);                                      // 6

    k_aggr<128, true, false><<<nb_ag128, 256>>>(hA, nullptr, hB, sAs, sAq, n); // 7
    k_bnfinal<<<1, DHID>>>(g1, be1, sAs, sAq, fn);                             // 8
    k_gemm_f16<128, 128, true><<<nb_gemm, 256>>>(hB, w2h, w2l, hA, n);         // 9
    k_aggr<128, true, false><<<nb_ag128, 256>>>(hA, nullptr, hB, sBs, sBq, n); // 10
    k_bnfinal<<<1, DHID>>>(g2, be2, sBs, sBq, fn);                             // 11
    k_gemm_f16<128, 64, true><<<nb_gemm, 256>>>(hB, w3h, w3l, hC, n);          // 12
    k_aggr<64, false, true><<<nb_ag64, 256>>>(hC, agg3, nullptr, nullptr, nullptr, n); // 13

    k_pool_final<<<nb_pool, DOUT>>>(agg3, batch, n, nb_pool, out, b3);         // 14
}

// round 17
// speedup vs baseline: 1.0936x; 1.0936x over previous
#include <cuda_runtime.h>
#include <cuda_fp16.h>
#include <math.h>
#include <stdint.h>

// ---------------- problem constants ----------------
#define NN 50000
#define EMAX 800000
#define DIN 256
#define DHID 128
#define DOUT 64
#define NGRAPH 16
#define BN_EPS 1e-5f
#define SCAN_B 256

// ---------------- device scratch ----------------
__device__ __align__(16) float g_dinv[NN];
__device__ __align__(16) int   g_cnt[NN];
__device__ __align__(16) int   g_off[NN + 1];
__device__ __align__(16) int   g_bsum[SCAN_B];
__device__ __align__(16) int2  g_edges[EMAX];
__device__ __align__(16) __half g_hA[NN * DHID];
__device__ __align__(16) __half g_hB[NN * DHID];
__device__ __align__(16) __half g_hC[NN * DOUT];
__device__ __align__(16) float g_agg3[NN * DOUT];
__device__ __align__(16) __half g_w1h[DIN * DHID],  g_w1l[DIN * DHID];
__device__ __align__(16) __half g_w2h[DHID * DHID], g_w2l[DHID * DHID];
__device__ __align__(16) __half g_w3h[DHID * DOUT], g_w3l[DHID * DOUT];
__device__ __align__(16) float g_statA_s[DHID], g_statA_q[DHID];   // layer1 stats
__device__ __align__(16) float g_statB_s[DHID], g_statB_q[DHID];   // layer2 stats
__device__ __align__(16) float g_bnsum[DHID];    // BN scale
__device__ __align__(16) float g_bnsq[DHID];     // BN shift
__device__ __align__(16) float g_pool[NGRAPH * DOUT];
__device__ __align__(16) float g_pcnt[NGRAPH];

#define WTOTAL (DIN * DHID + DHID * DHID + DHID * DOUT)

// ---------------- W prep (ALL weights, one launch) ----------------
__global__ void k_wprep_all(const float* __restrict__ W1,
                            const float* __restrict__ W2,
                            const float* __restrict__ W3) {
    int i = blockIdx.x * blockDim.x + threadIdx.x;
    const float* W; __half* Hh; __half* Hl; int K, N, j;
    if (i < DIN * DHID) {
        W = W1; Hh = g_w1h; Hl = g_w1l; K = DIN; N = DHID; j = i;
    } else if (i < DIN * DHID + DHID * DHID) {
        W = W2; Hh = g_w2h; Hl = g_w2l; K = DHID; N = DHID; j = i - DIN * DHID;
    } else if (i < WTOTAL) {
        W = W3; Hh = g_w3h; Hl = g_w3l; K = DHID; N = DOUT;
        j = i - DIN * DHID - DHID * DHID;
    } else return;
    int k = j / N, n = j % N;
    float v = W[j];
    __half h = __float2half_rn(v);
    Hh[n * K + k] = h;
    Hl[n * K + k] = __float2half_rn(v - __half2float(h));
}

// ---------------- init ----------------
__global__ void k_init(int n) {
    int i = blockIdx.x * blockDim.x + threadIdx.x;
    if (i < n) g_cnt[i] = 0;
    if (i < DHID) {
        g_statA_s[i] = 0.0f; g_statA_q[i] = 0.0f;
        g_statB_s[i] = 0.0f; g_statB_q[i] = 0.0f;
    }
    if (i < NGRAPH * DOUT) g_pool[i] = 0.0f;
    if (i < NGRAPH) g_pcnt[i] = 0.0f;
}

__global__ void k_cnt(const int* __restrict__ dst, int e, int n) {
    int i = blockIdx.x * blockDim.x + threadIdx.x;
    if (i < e) {
        int d = dst[i];
        if ((unsigned)d < (unsigned)n) atomicAdd(&g_cnt[d], 1);
    }
}

// ---------------- scan phase A (+ dinv fused) ----------------
__global__ void k_scanA(int n) {
    __shared__ int sh[SCAN_B];
    int t = threadIdx.x;
    int i = blockIdx.x * SCAN_B + t;
    int cv = (i < n) ? g_cnt[i] : 0;
    if (i < n) g_dinv[i] = rsqrtf((float)cv + 1.0f);   // deg = cnt + 1
    sh[t] = cv;
    __syncthreads();
#pragma unroll
    for (int d = SCAN_B / 2; d > 0; d >>= 1) {
        if (t < d) sh[t] += sh[t + d];
        __syncthreads();
    }
    if (t == 0) g_bsum[blockIdx.x] = sh[0];
}

__global__ void k_scanB(int nblocks, int n) {
    __shared__ int sh[SCAN_B];
    int t = threadIdx.x;
    int v = (t < nblocks) ? g_bsum[t] : 0;
    sh[t] = v;
    __syncthreads();
#pragma unroll
    for (int d = 1; d < SCAN_B; d <<= 1) {
        int x = (t >= d) ? sh[t - d] : 0;
        __syncthreads();
        sh[t] += x;
        __syncthreads();
    }
    if (t < nblocks) g_bsum[t] = sh[t] - v;
    if (t == SCAN_B - 1) g_off[n] = sh[t];
}

__global__ void k_scanC(int n) {
    __shared__ int sh[SCAN_B];
    int t = threadIdx.x;
    int i = blockIdx.x * SCAN_B + t;
    int v = (i < n) ? g_cnt[i] : 0;
    sh[t] = v;
    __syncthreads();
#pragma unroll
    for (int d = 1; d < SCAN_B; d <<= 1) {
        int x = (t >= d) ? sh[t - d] : 0;
        __syncthreads();
        sh[t] += x;
        __syncthreads();
    }
    if (i < n) {
        int off = g_bsum[blockIdx.x] + sh[t] - v;
        g_off[i] = off;
        g_cnt[i] = off;
    }
}

__global__ void k_fill(const int* __restrict__ src, const int* __restrict__ dst,
                       int e, int n) {
    int i = blockIdx.x * blockDim.x + threadIdx.x;
    if (i >= e) return;
    int s = src[i], d = dst[i];
    if ((unsigned)s >= (unsigned)n || (unsigned)d >= (unsigned)n) return;
    float w = g_dinv[s] * g_dinv[d];
    int pos = atomicAdd(&g_cnt[d], 1);
    g_edges[pos] = make_int2(s, __float_as_int(w));
}

// ---------------- mma / ldmatrix helpers ----------------
#define MMA_F16(d, a, b0, b1)                                               \
    asm volatile(                                                           \
        "mma.sync.aligned.m16n8k16.row.col.f32.f16.f16.f32 "                \
        "{%0,%1,%2,%3}, {%4,%5,%6,%7}, {%8,%9}, {%0,%1,%2,%3};"             \
        : "+f"((d)[0]), "+f"((d)[1]), "+f"((d)[2]), "+f"((d)[3])            \
        : "r"((a)[0]), "r"((a)[1]), "r"((a)[2]), "r"((a)[3]),               \
          "r"(b0), "r"(b1))

__device__ __forceinline__ void ldsm_x4(uint32_t addr, unsigned* r) {
    asm volatile("ldmatrix.sync.aligned.m8n8.x4.shared.b16 {%0,%1,%2,%3}, [%4];"
                 : "=r"(r[0]), "=r"(r[1]), "=r"(r[2]), "=r"(r[3]) : "r"(addr));
}

// ---------------- tensor-core GEMM: 2-pass fp16, ldmatrix fragments --------
// OUT (fp16) = T(X) @ W.  T: identity or BN-affine(g_bnsum/g_bnsq)+ReLU.
// X input fp32 (HIN=false) or fp16 (HIN=true).
template <int KDIM, int NOUT, bool BNRELU, bool HIN>
__global__ void __launch_bounds__(256, 2)
k_gemm_f16(const void* Xv, const __half* __restrict__ Whg,
           const __half* __restrict__ Wlg, __half* __restrict__ OUT, int nrows) {
    constexpr int BM = 128, BK = 16, KS = 24;     // 48B row stride
    constexpr int hN = NOUT / 2;
    constexpr int NT = hN / 8;                    // 8 or 4
    constexpr int NP = NT / 2;                    // ldmatrix n-pairs (4 or 2)
    constexpr int MT = 2;
    constexpr int KT = KDIM / BK;
    constexpr int WL = (NOUT == 128) ? 8 : 4;

    __shared__ __half Xs[2][BM][KS];
    __shared__ __half Wh[2][NOUT][KS], Wl[2][NOUT][KS];

    const float*  Xf = (const float*)Xv;
    const __half* Xp = (const __half*)Xv;

    const int tid = threadIdx.x;
    const int lane = tid & 31;
    const int wid = tid >> 5;
    const int wm = wid & 3, wn = wid >> 2;
    const int row0 = blockIdx.x * BM;

    const int xr = tid >> 1;
    const int xkp = (tid & 1) * 8;
    const int wr = (NOUT == 128) ? (tid >> 1) : (tid >> 2);
    const int wkp = (NOUT == 128) ? (tid & 1) * 8 : (tid & 3) * 4;

    // ldmatrix per-lane byte offsets (within a stage)
    const int grp = lane >> 3, lr = lane & 7;
    const uint32_t xsBase = (uint32_t)__cvta_generic_to_shared(&Xs[0][0][0]);
    const uint32_t whBase = (uint32_t)__cvta_generic_to_shared(&Wh[0][0][0]);
    const uint32_t wlBase = (uint32_t)__cvta_generic_to_shared(&Wl[0][0][0]);
    const uint32_t xsStage = BM * KS * 2;
    const uint32_t wStage  = NOUT * KS * 2;
    uint32_t aOff[MT];
#pragma unroll
    for (int mt = 0; mt < MT; mt++) {
        int r = wm * 32 + mt * 16 + (grp & 1) * 8 + lr;
        aOff[mt] = (uint32_t)(r * KS * 2 + (grp >> 1) * 16);
    }
    uint32_t bOff[NP];
#pragma unroll
    for (int p = 0; p < NP; p++) {
        int r = wn * hN + p * 16 + (grp >> 1) * 8 + lr;
        bOff[p] = (uint32_t)(r * KS * 2 + (grp & 1) * 16);
    }

    float acc[MT][NT][4] = {};
    float xv[8];
    __half wvh[WL], wvl[WL];

    auto fetch = [&](int kb) {
        int row = row0 + xr;
        if (HIN) {
            uint4 u = make_uint4(0, 0, 0, 0);
            if (row < nrows)
                u = *reinterpret_cast<const uint4*>(&Xp[(size_t)row * KDIM + kb + xkp]);
            const __half2* hp = reinterpret_cast<const __half2*>(&u);
#pragma unroll
            for (int j = 0; j < 4; j++) {
                float2 f = __half22float2(hp[j]);
                xv[2 * j] = f.x; xv[2 * j + 1] = f.y;
            }
        } else {
#pragma unroll
            for (int i = 0; i < 2; i++) {
                float4 v = make_float4(0.f, 0.f, 0.f, 0.f);
                if (row < nrows)
                    v = *reinterpret_cast<const float4*>(
                        &Xf[(size_t)row * KDIM + kb + xkp + i * 4]);
                xv[i * 4 + 0] = v.x; xv[i * 4 + 1] = v.y;
                xv[i * 4 + 2] = v.z; xv[i * 4 + 3] = v.w;
            }
        }
        const __half* ph = &Whg[(size_t)wr * KDIM + kb + wkp];
        const __half* pl = &Wlg[(size_t)wr * KDIM + kb + wkp];
        if (WL == 8) {
            *reinterpret_cast<uint4*>(wvh) = *reinterpret_cast<const uint4*>(ph);
            *reinterpret_cast<uint4*>(wvl) = *reinterpret_cast<const uint4*>(pl);
        } else {
            *reinterpret_cast<uint2*>(wvh) = *reinterpret_cast<const uint2*>(ph);
            *reinterpret_cast<uint2*>(wvl) = *reinterpret_cast<const uint2*>(pl);
        }
    };

    auto stage = [&](int kb, int s) {
        __half hx[8];
#pragma unroll
        for (int j = 0; j < 8; j++) {
            float v = xv[j];
            if (BNRELU)
                v = fmaxf(fmaf(v, g_bnsum[kb + xkp + j], g_bnsq[kb + xkp + j]), 0.f);
            hx[j] = __float2half_rn(v);
        }
        *reinterpret_cast<uint4*>(&Xs[s][xr][xkp]) = *reinterpret_cast<uint4*>(hx);
        if (WL == 8) {
            *reinterpret_cast<uint4*>(&Wh[s][wr][wkp]) = *reinterpret_cast<uint4*>(wvh);
            *reinterpret_cast<uint4*>(&Wl[s][wr][wkp]) = *reinterpret_cast<uint4*>(wvl);
        } else {
            *reinterpret_cast<uint2*>(&Wh[s][wr][wkp]) = *reinterpret_cast<uint2*>(wvh);
            *reinterpret_cast<uint2*>(&Wl[s][wr][wkp]) = *reinterpret_cast<uint2*>(wvl);
        }
    };

    fetch(0);
    stage(0, 0);
    __syncthreads();

    for (int kt = 0; kt < KT; kt++) {
        const int s = kt & 1;
        const bool more = (kt + 1 < KT);
        if (more) fetch((kt + 1) * BK);

        unsigned ah[MT][4];
#pragma unroll
        for (int mt = 0; mt < MT; mt++)
            ldsm_x4(xsBase + s * xsStage + aOff[mt], ah[mt]);

#pragma unroll
        for (int p = 0; p < NP; p++) {
            unsigned bh[4], bl[4];
            ldsm_x4(whBase + s * wStage + bOff[p], bh);
            ldsm_x4(wlBase + s * wStage + bOff[p], bl);
#pragma unroll
            for (int mt = 0; mt < MT; mt++) {
                MMA_F16(acc[mt][2 * p],     ah[mt], bh[0], bh[1]);
                MMA_F16(acc[mt][2 * p + 1], ah[mt], bh[2], bh[3]);
            }
#pragma unroll
            for (int mt = 0; mt < MT; mt++) {
                MMA_F16(acc[mt][2 * p],     ah[mt], bl[0], bl[1]);
                MMA_F16(acc[mt][2 * p + 1], ah[mt], bl[2], bl[3]);
            }
        }

        if (more) stage((kt + 1) * BK, s ^ 1);
        __syncthreads();
    }

    const int rfo = lane >> 2;
#pragma unroll
    for (int mt = 0; mt < MT; mt++) {
        int r0 = row0 + wm * 32 + mt * 16 + rfo;
        int r1 = r0 + 8;
#pragma unroll
        for (int nt = 0; nt < NT; nt++) {
            int col = wn * hN + nt * 8 + (lane & 3) * 2;
            if (r0 < nrows)
                *reinterpret_cast<__half2*>(&OUT[(size_t)r0 * NOUT + col]) =
                    __floats2half2_rn(acc[mt][nt][0], acc[mt][nt][1]);
            if (r1 < nrows)
                *reinterpret_cast<__half2*>(&OUT[(size_t)r1 * NOUT + col]) =
                    __floats2half2_rn(acc[mt][nt][2], acc[mt][nt][3]);
        }
    }
}

// ---------------- fp16 gather helper ----------------
__device__ __forceinline__ void fma8h(uint4 u, float w, float* acc) {
    const __half2* hp = reinterpret_cast<const __half2*>(&u);
#pragma unroll
    for (int j = 0; j < 4; j++) {
        float2 f = __half22float2(hp[j]);
        acc[2 * j]     = fmaf(f.x, w, acc[2 * j]);
        acc[2 * j + 1] = fmaf(f.y, w, acc[2 * j + 1]);
    }
}

// ---------------- CSR aggregation (fp16 gather, fp32 accumulate) ------------
template <int NOUT, bool BNSTAT, bool OUTF32>
__global__ void __launch_bounds__(256, 4)
k_aggr(const __half* __restrict__ h, float* __restrict__ outf,
       __half* __restrict__ outh, float* __restrict__ stat_s,
       float* __restrict__ stat_q, int n) {
    constexpr int LPN = NOUT / 8;
    constexpr int NPW = 32 / LPN;
    constexpr int NPB = 8 * NPW;
    __shared__ float ss[BNSTAT ? DHID : 1], sq[BNSTAT ? DHID : 1];

    int tid = threadIdx.x;
    int warp = tid >> 5, lane = tid & 31;
    if (BNSTAT) {
        if (tid < NOUT) { ss[tid] = 0.0f; sq[tid] = 0.0f; }
        __syncthreads();
    }

    int node = blockIdx.x * NPB + warp * NPW + lane / LPN;
    int c = (lane % LPN) * 8;
    float acc[8] = {};
    bool active = (node < n);

    if (active) {
        float di = g_dinv[node];
        di *= di;
        {
            uint4 u = *reinterpret_cast<const uint4*>(&h[(size_t)node * NOUT + c]);
            const __half2* hp = reinterpret_cast<const __half2*>(&u);
#pragma unroll
            for (int j = 0; j < 4; j++) {
                float2 f = __half22float2(hp[j]);
                acc[2 * j] = f.x * di;
                acc[2 * j + 1] = f.y * di;
            }
        }

        int i = g_off[node], e1 = g_off[node + 1];
        for (; i + 4 <= e1; i += 4) {
            int2 e0 = g_edges[i + 0];
            int2 e1r = g_edges[i + 1];
            int2 e2 = g_edges[i + 2];
            int2 e3 = g_edges[i + 3];
            uint4 u0 = *reinterpret_cast<const uint4*>(&h[(size_t)e0.x * NOUT + c]);
            uint4 u1 = *reinterpret_cast<const uint4*>(&h[(size_t)e1r.x * NOUT + c]);
            uint4 u2 = *reinterpret_cast<const uint4*>(&h[(size_t)e2.x * NOUT + c]);
            uint4 u3 = *reinterpret_cast<const uint4*>(&h[(size_t)e3.x * NOUT + c]);
            fma8h(u0, __int_as_float(e0.y), acc);
            fma8h(u1, __int_as_float(e1r.y), acc);
            fma8h(u2, __int_as_float(e2.y), acc);
            fma8h(u3, __int_as_float(e3.y), acc);
        }
        if (i + 2 <= e1) {
            int2 e0 = g_edges[i + 0];
            int2 e1r = g_edges[i + 1];
            uint4 u0 = *reinterpret_cast<const uint4*>(&h[(size_t)e0.x * NOUT + c]);
            uint4 u1 = *reinterpret_cast<const uint4*>(&h[(size_t)e1r.x * NOUT + c]);
            fma8h(u0, __int_as_float(e0.y), acc);
            fma8h(u1, __int_as_float(e1r.y), acc);
            i += 2;
        }
        if (i < e1) {
            int2 e = g_edges[i];
            uint4 u = *reinterpret_cast<const uint4*>(&h[(size_t)e.x * NOUT + c]);
            fma8h(u, __int_as_float(e.y), acc);
        }

        if (OUTF32) {
            float4 a = make_float4(acc[0], acc[1], acc[2], acc[3]);
            float4 b = make_float4(acc[4], acc[5], acc[6], acc[7]);
            *reinterpret_cast<float4*>(&outf[(size_t)node * NOUT + c]) = a;
            *reinterpret_cast<float4*>(&outf[(size_t)node * NOUT + c + 4]) = b;
        } else {
            uint4 o;
            __half2* op = reinterpret_cast<__half2*>(&o);
            op[0] = __floats2half2_rn(acc[0], acc[1]);
            op[1] = __floats2half2_rn(acc[2], acc[3]);
            op[2] = __floats2half2_rn(acc[4], acc[5]);
            op[3] = __floats2half2_rn(acc[6], acc[7]);
            *reinterpret_cast<uint4*>(&outh[(size_t)node * NOUT + c]) = o;
        }
    }

    if (BNSTAT) {
        if (active) {
#pragma unroll
            for (int j = 0; j < 8; j++) {
                atomicAdd(&ss[c + j], acc[j]);
                atomicAdd(&sq[c + j], acc[j] * acc[j]);
            }
        }
        __syncthreads();
        if (tid < NOUT) {
            atomicAdd(&stat_s[tid], ss[tid]);
            atomicAdd(&stat_q[tid], sq[tid]);
        }
    }
}

// ---------------- BN finalize: raw stats -> (scale, shift) ----------------
__global__ void k_bnfinal(const float* __restrict__ gam, const float* __restrict__ bet,
                          const float* __restrict__ stat_s,
                          const float* __restrict__ stat_q, float n) {
    int c = threadIdx.x;  // 128
    float mu = stat_s[c] / n;
    float var = stat_q[c] / n - mu * mu;
    float sc = rsqrtf(var + BN_EPS) * gam[c];
    g_bnsum[c] = sc;
    g_bnsq[c] = bet[c] - mu * sc;
}

// ---------------- pool: batch sorted -> run-length accumulate ----------------
#define POOL_CHUNK 128
__global__ void k_pool(const float* __restrict__ h, const int* __restrict__ batch, int n) {
    int col = threadIdx.x;  // 64
    int r0 = blockIdx.x * POOL_CHUNK;
    if (r0 >= n) return;
    int r1 = min(r0 + POOL_CHUNK, n);
    int cur = batch[r0] & (NGRAPH - 1);
    float acc = 0.0f, cacc = 0.0f;
    for (int r = r0; r < r1; r++) {
        int g = batch[r] & (NGRAPH - 1);
        if (g != cur) {
            atomicAdd(&g_pool[cur * DOUT + col], acc);
            if (col == 0) atomicAdd(&g_pcnt[cur], cacc);
            acc = 0.0f; cacc = 0.0f; cur = g;
        }
        acc += h[(size_t)r * DOUT + col];
        cacc += 1.0f;
    }
    atomicAdd(&g_pool[cur * DOUT + col], acc);
    if (col == 0) atomicAdd(&g_pcnt[cur], cacc);
}

__global__ void k_final(float* __restrict__ out, const float* __restrict__ b3) {
    int t = threadIdx.x;  // 1024
    int g = t / DOUT;
    int c = t % DOUT;
    float cnt = g_pcnt[g];
    out[t] = (cnt > 0.0f) ? (g_pool[t] / cnt + b3[c]) : 0.0f;
}

// ============================================================================
extern "C" void kernel_launch(void* const* d_in, const int* in_sizes, int n_in,
                              void* d_out, int out_size) {
    const float* x     = (const float*)d_in[0];
    const int*   ei    = (const int*)d_in[1];   // int64 coerced to int32
    const int*   batch = (const int*)d_in[2];
    const float* W1    = (const float*)d_in[3];
    const float* W2    = (const float*)d_in[5];
    const float* W3    = (const float*)d_in[7];
    const float* b3    = (const float*)d_in[8];
    const float* g1    = (const float*)d_in[9];
    const float* be1   = (const float*)d_in[10];
    const float* g2    = (const float*)d_in[11];
    const float* be2   = (const float*)d_in[12];
    float* out = (float*)d_out;

    const int n = in_sizes[2];       // 50000
    const int E = in_sizes[1] / 2;   // 800000
    const int* src = ei;
    const int* dst = ei + E;

    __half* hA; __half* hB; __half* hC; float* agg3;
    cudaGetSymbolAddress((void**)&hA, g_hA);
    cudaGetSymbolAddress((void**)&hB, g_hB);
    cudaGetSymbolAddress((void**)&hC, g_hC);
    cudaGetSymbolAddress((void**)&agg3, g_agg3);
    __half *w1h, *w1l, *w2h, *w2l, *w3h, *w3l;
    cudaGetSymbolAddress((void**)&w1h, g_w1h);
    cudaGetSymbolAddress((void**)&w1l, g_w1l);
    cudaGetSymbolAddress((void**)&w2h, g_w2h);
    cudaGetSymbolAddress((void**)&w2l, g_w2l);
    cudaGetSymbolAddress((void**)&w3h, g_w3h);
    cudaGetSymbolAddress((void**)&w3l, g_w3l);
    float *sAs, *sAq, *sBs, *sBq;
    cudaGetSymbolAddress((void**)&sAs, g_statA_s);
    cudaGetSymbolAddress((void**)&sAq, g_statA_q);
    cudaGetSymbolAddress((void**)&sBs, g_statB_s);
    cudaGetSymbolAddress((void**)&sBq, g_statB_q);

    const int TB = 256;
    int nb_n    = (n + TB - 1) / TB;
    int nb_e    = (E + TB - 1) / TB;
    int nb_scan = (n + SCAN_B - 1) / SCAN_B;
    int nb_gemm = (n + 127) / 128;
    int nb_ag128 = (n + 15) / 16;
    int nb_ag64  = (n + 31) / 32;
    int nb_pool  = (n + POOL_CHUNK - 1) / POOL_CHUNK;
    float fn = (float)n;

    // r13 structure (best measured) + ldmatrix GEMM. gemm1 early for ncu.
    k_wprep_all<<<(WTOTAL + TB - 1) / TB, TB>>>(W1, W2, W3);                   // 1
    k_init<<<nb_n, TB>>>(n);                                                   // 2
    k_cnt<<<nb_e, TB>>>(dst, E, n);                                            // 3
    k_scanA<<<nb_scan, SCAN_B>>>(n);                                           // 4
    k_scanB<<<1, SCAN_B>>>(nb_scan, n);                                        // 5
    k_gemm_f16<256, 128, false, false><<<nb_gemm, 256>>>(x, w1h, w1l, hA, n);  // 6
    k_scanC<<<nb_scan, SCAN_B>>>(n);                                           // 7
    k_fill<<<nb_e, TB>>>(src, dst, E, n);                                      // 8

    // ---- layer 1 aggregation + BN ----
    k_aggr<128, true, false><<<nb_ag128, 256>>>(hA, nullptr, hB, sAs, sAq, n); // 9
    k_bnfinal<<<1, DHID>>>(g1, be1, sAs, sAq, fn);                             // 10

    // ---- layer 2 ----
    k_gemm_f16<128, 128, true, true><<<nb_gemm, 256>>>(hB, w2h, w2l, hA, n);   // 11
    k_aggr<128, true, false><<<nb_ag128, 256>>>(hA, nullptr, hB, sBs, sBq, n); // 12
    k_bnfinal<<<1, DHID>>>(g2, be2, sBs, sBq, fn);                             // 13

    // ---- layer 3 ----
    k_gemm_f16<128, 64, true, true><<<nb_gemm, 256>>>(hB, w3h, w3l, hC, n);    // 14
    k_aggr<64, false, true><<<nb_ag64, 256>>>(hC, agg3, nullptr, nullptr, nullptr, n); // 15

    // ---- mean pool + bias ----
    k_pool<<<nb_pool, DOUT>>>(agg3, batch, n);                                 // 16
    k_final<<<1, NGRAPH * DOUT>>>(out, b3);                                    // 17
}